// round 2
// baseline (speedup 1.0000x reference)
#include <cuda_runtime.h>
#include <cstdint>
#include <cstddef>

#define LOG2E_F 1.4426950408889634f
#define LN2_F   0.6931471805599453f

__device__ __forceinline__ float ex2f_(float x) {
    float y; asm("ex2.approx.ftz.f32 %0, %1;" : "=f"(y) : "f"(x)); return y;
}
__device__ __forceinline__ float lg2f_(float x) {
    float y; asm("lg2.approx.f32 %0, %1;" : "=f"(y) : "f"(x)); return y;
}
__device__ __forceinline__ unsigned long long pk2(float lo, float hi) {
    unsigned long long r; asm("mov.b64 %0, {%1, %2};" : "=l"(r) : "f"(lo), "f"(hi)); return r;
}
__device__ __forceinline__ void upk2(unsigned long long v, float& lo, float& hi) {
    asm("mov.b64 {%0, %1}, %2;" : "=f"(lo), "=f"(hi) : "l"(v));
}
__device__ __forceinline__ void fma2_(unsigned long long& acc, unsigned long long a, unsigned long long b) {
    asm("fma.rn.f32x2 %0, %1, %2, %0;" : "+l"(acc) : "l"(a), "l"(b));
}
__device__ __forceinline__ unsigned long long add2_(unsigned long long a, unsigned long long b) {
    unsigned long long r; asm("add.rn.f32x2 %0, %1, %2;" : "=l"(r) : "l"(a), "l"(b)); return r;
}

// One CTA per batch. 256 threads: cp = tid>>2 -> column pair (j0=2cp, j0+1),
// ich = tid&3 -> 32-wide chunk of "from" states. E = exp(logA) lives in
// registers, packed {a_j0, a_j0+1} per i. Forward vector kept linear-domain,
// UNSCALED in double-buffered smem (duplicated {v,v} for LDS.64 -> fma.f32x2);
// the uniform power-of-2 rescale (exact, from the exponent field of the block
// max, published via double-buffered smem) is folded into the accumulator the
// FOLLOWING step -> exactly one __syncthreads per time step, and zero
// transcendentals on the recurrence critical path.
__global__ __launch_bounds__(256, 1)
void crf_fwd_kernel(const float* __restrict__ obs,
                    const float* __restrict__ logA,
                    float* __restrict__ out,
                    int T)
{
    constexpr int S = 128;
    __shared__ unsigned long long v2[2][4 * 33];  // [buf][chunk*33 + (i&31)] = {v_i, v_i}
    __shared__ float wm[2][8];                    // [buf][warp] partial maxes (raw)
    __shared__ float wsum[4];

    const int tid  = threadIdx.x;
    const int b    = blockIdx.x;
    const int cp   = tid >> 2;
    const int ich  = tid & 3;
    const int j0   = cp * 2;
    const int warp = tid >> 5;
    const int slot = ((j0 >> 5) * 33) + (j0 & 31);   // j0 even -> slot+1 same chunk

    const float* ob = obs + (size_t)b * (size_t)T * S + j0;

    // E[i][j0], E[i][j0+1] for i in [32*ich, 32*ich+32), packed per i.
    unsigned long long A[32];
#pragma unroll
    for (int k = 0; k < 32; ++k) {
        const float2 e = *reinterpret_cast<const float2*>(logA + (ich * 32 + k) * S + j0);
        A[k] = pk2(ex2f_(e.x * LOG2E_F), ex2f_(e.y * LOG2E_F));
    }

    // ---- t = 0: w_0 = exp(obs[0]) stored raw ----
    const float2 o0 = *reinterpret_cast<const float2*>(ob);
    const float u0 = ex2f_(o0.x * LOG2E_F);
    const float u1 = ex2f_(o0.y * LOG2E_F);
    {
        const int im = __reduce_max_sync(0xffffffffu, __float_as_int(fmaxf(u0, u1)));
        if ((tid & 31) == 0) wm[0][warp] = __int_as_float(im);
        if (ich == 0) { v2[0][slot] = pk2(u0, u0); v2[0][slot + 1] = pk2(u1, u1); }
    }
    float2 oL = (T > 1) ? *reinterpret_cast<const float2*>(ob + S) : o0;  // obs[1]
    int L = 0;   // exact accumulated log2 scale (identical in every thread)
    __syncthreads();

    // ---- scan t = 1 .. T-1 (ONE barrier per step) ----
    for (int t = 1; t < T; ++t) {
        const int cb = (t - 1) & 1, nb = t & 1;

        // previous step's block max (raw) -> exponent-only scale, off chain
        const float m = fmaxf(fmaxf(fmaxf(wm[cb][0], wm[cb][1]), fmaxf(wm[cb][2], wm[cb][3])),
                              fmaxf(fmaxf(wm[cb][4], wm[cb][5]), fmaxf(wm[cb][6], wm[cb][7])));
        // observation factor early so MUFU latency overlaps the matvec
        const float p0 = ex2f_(oL.x * LOG2E_F);
        const float p1 = ex2f_(oL.y * LOG2E_F);
        // prefetch obs[t+1] a full step ahead
        float2 oN = oL;
        if (t + 1 < T) oN = *reinterpret_cast<const float2*>(ob + (size_t)(t + 1) * S);

        // matvec over this thread's 32-i chunk: two independent packed chains
        unsigned long long acca = 0ull, accb = 0ull;
        const unsigned long long* Vb = &v2[cb][ich * 33];
#pragma unroll
        for (int k = 0; k < 16; ++k) {
            fma2_(acca, Vb[2 * k],     A[2 * k]);
            fma2_(accb, Vb[2 * k + 1], A[2 * k + 1]);
        }
        float acc0, acc1;
        upk2(add2_(acca, accb), acc0, acc1);
        // butterfly across the 4 i-chunks (tid^1, tid^2 flip only ich)
        acc0 += __shfl_xor_sync(0xffffffffu, acc0, 1);
        acc1 += __shfl_xor_sync(0xffffffffu, acc1, 1);
        acc0 += __shfl_xor_sync(0xffffffffu, acc0, 2);
        acc1 += __shfl_xor_sync(0xffffffffu, acc1, 2);

        const int e = ((__float_as_int(m) >> 23) & 0xFF) - 127;
        L += e;
        const float sc = __int_as_float((127 - e) << 23);   // exact 2^-e
        const float un0 = acc0 * (p0 * sc);
        const float un1 = acc1 * (p1 * sc);

        const int im = __reduce_max_sync(0xffffffffu, __float_as_int(fmaxf(un0, un1)));
        if ((tid & 31) == 0) wm[nb][warp] = __int_as_float(im);
        if (ich == 0) { v2[nb][slot] = pk2(un0, un0); v2[nb][slot + 1] = pk2(un1, un1); }
        oL = oN;
        __syncthreads();
    }

    // ---- finalize: out[b] = -ln2 * (log2(sum_j w) + L) ----
    const int fb = (T - 1) & 1;
    float vv = 0.f;
    if (tid < 128) {
        float lo, hi;
        upk2(v2[fb][((tid >> 5) * 33) + (tid & 31)], lo, hi);
        vv = lo; (void)hi;
    }
#pragma unroll
    for (int o = 16; o; o >>= 1) vv += __shfl_xor_sync(0xffffffffu, vv, o);
    if (tid < 128 && (tid & 31) == 0) wsum[tid >> 5] = vv;
    __syncthreads();
    if (tid == 0) {
        const float s = (wsum[0] + wsum[1]) + (wsum[2] + wsum[3]);
        out[b] = -LN2_F * (lg2f_(s) + (float)L);
    }
}

extern "C" void kernel_launch(void* const* d_in, const int* in_sizes, int n_in,
                              void* d_out, int out_size)
{
    const float* obs  = (const float*)d_in[0];   // [B, T, S] f32
    const float* logA = (const float*)d_in[1];   // [S, S]   f32
    float* out = (float*)d_out;                  // [B]      f32

    const int B = out_size;
    const int S = 128;
    const int T = in_sizes[0] / (B * S);

    crf_fwd_kernel<<<B, 256>>>(obs, logA, out, T);
}

// round 3
// speedup vs baseline: 2.3655x; 2.3655x over previous
#include <cuda_runtime.h>
#include <cstdint>
#include <cstddef>

#define LOG2E_F 1.4426950408889634f
#define LN2_F   0.6931471805599453f

__device__ __forceinline__ float ex2f_(float x) {
    float y; asm("ex2.approx.ftz.f32 %0, %1;" : "=f"(y) : "f"(x)); return y;
}
__device__ __forceinline__ float lg2f_(float x) {
    float y; asm("lg2.approx.f32 %0, %1;" : "=f"(y) : "f"(x)); return y;
}
__device__ __forceinline__ unsigned long long pk2(float lo, float hi) {
    unsigned long long r; asm("mov.b64 %0, {%1, %2};" : "=l"(r) : "f"(lo), "f"(hi)); return r;
}
__device__ __forceinline__ void upk2(unsigned long long v, float& lo, float& hi) {
    asm("mov.b64 {%0, %1}, %2;" : "=f"(lo), "=f"(hi) : "l"(v));
}
__device__ __forceinline__ void fma2_(unsigned long long& acc, unsigned long long a, unsigned long long b) {
    asm("fma.rn.f32x2 %0, %1, %2, %0;" : "+l"(acc) : "l"(a), "l"(b));
}
__device__ __forceinline__ unsigned long long add2_(unsigned long long a, unsigned long long b) {
    unsigned long long r; asm("add.rn.f32x2 %0, %1, %2;" : "=l"(r) : "l"(a), "l"(b)); return r;
}

// One CTA per batch, 256 threads. cp = tid>>2 -> column pair (j0 = 2cp, j0+1),
// ich = tid&3 -> 32-wide "from"-state chunk. E = exp(logA) in registers,
// packed by consecutive i-PAIRS: fma.rn.f32x2 with {v_2k, v_2k+1} loaded as a
// single natural LDS.64 (no duplication) -> 16 LDS.64 + 32 fma2 per thread/step.
// Forward vector kept linear-domain in double-buffered padded smem; exact
// power-of-2 renorm only every 8 steps (publish block max at t%8==0, fold
// 2^-e into the accumulator at t%8==1). One __syncthreads per step.
// obs is streamed through a 4-deep register prefetch ring (unroll 4) so the
// per-step DRAM latency (~600-800cyc) is fully hidden.
__global__ __launch_bounds__(256, 1)
void crf_fwd_kernel(const float* __restrict__ obs,
                    const float* __restrict__ logA,
                    float* __restrict__ out,
                    int T)
{
    constexpr int S = 128;
    // chunk stride 34 floats: keeps float2 alignment and puts the 4 broadcast
    // addresses of each LDS.64 on distinct bank pairs (34 mod 32 = 2).
    __shared__ __align__(16) float v_sm[2][4 * 34];
    __shared__ float wm[8];
    __shared__ float wsum[4];

    const int tid  = threadIdx.x;
    const int b    = blockIdx.x;
    const int cp   = tid >> 2;
    const int ich  = tid & 3;
    const int j0   = cp * 2;
    const int warp = tid >> 5;
    const int wslot = ((j0 >> 5) * 34) + (j0 & 31);   // write slot (even -> 8B aligned)

    const float* ob = obs + (size_t)b * (size_t)T * S + j0;

    // A0[k] = {E[i0+2k][j0],   E[i0+2k+1][j0]}
    // A1[k] = {E[i0+2k][j0+1], E[i0+2k+1][j0+1]},  i0 = 32*ich
    unsigned long long A0[16], A1[16];
#pragma unroll
    for (int k = 0; k < 16; ++k) {
        const int i0 = ich * 32 + 2 * k;
        const float2 ea = *reinterpret_cast<const float2*>(logA + (size_t)i0 * S + j0);
        const float2 eb = *reinterpret_cast<const float2*>(logA + (size_t)(i0 + 1) * S + j0);
        A0[k] = pk2(ex2f_(ea.x * LOG2E_F), ex2f_(eb.x * LOG2E_F));
        A1[k] = pk2(ex2f_(ea.y * LOG2E_F), ex2f_(eb.y * LOG2E_F));
    }

    // ---- t = 0: u = exp(obs[0]) stored raw; publish block max (t%8==0) ----
    const float2 o0 = *reinterpret_cast<const float2*>(ob);
    const float u0 = ex2f_(o0.x * LOG2E_F);
    const float u1 = ex2f_(o0.y * LOG2E_F);
    {
        const int im = __reduce_max_sync(0xffffffffu, __float_as_int(fmaxf(u0, u1)));
        if ((tid & 31) == 0) wm[warp] = __int_as_float(im);
        if (ich == 0) {
            float2 w; w.x = u0; w.y = u1;
            *reinterpret_cast<float2*>(&v_sm[0][wslot]) = w;
        }
    }

    // 4-deep obs prefetch ring: slot = t & 3 holds obs[t], t consumed ascending.
    float2 oB[4];
#pragma unroll
    for (int k = 1; k <= 4; ++k)
        oB[k & 3] = (k < T) ? __ldcs(reinterpret_cast<const float2*>(ob + (size_t)k * S)) : o0;

    int L = 0;                 // exact accumulated log2 scale (uniform across block)
    __syncthreads();

    // ---- scan t = 1 .. T-1, ONE barrier per step ----
#pragma unroll 4
    for (int t = 1; t < T; ++t) {
        const int cb = (t - 1) & 1, nb = t & 1;

        const float2 oc = oB[t & 3];
        if (t + 4 < T)
            oB[t & 3] = __ldcs(reinterpret_cast<const float2*>(ob + (size_t)(t + 4) * S));

        // observation factor early (MUFU latency hides under the matvec)
        const float p0 = ex2f_(oc.x * LOG2E_F);
        const float p1 = ex2f_(oc.y * LOG2E_F);

        // fold previous publish's exact 2^-e every 8th step
        float sc = 1.0f;
        if ((t & 7) == 1) {
            const float m = fmaxf(fmaxf(fmaxf(wm[0], wm[1]), fmaxf(wm[2], wm[3])),
                                  fmaxf(fmaxf(wm[4], wm[5]), fmaxf(wm[6], wm[7])));
            const int e = ((__float_as_int(m) >> 23) & 0xFF) - 127;
            L += e;
            sc = __int_as_float((127 - e) << 23);   // exact 2^-e
        }

        // matvec over this thread's 32-i chunk, i-pair packed, 2 chains/column
        const unsigned long long* V =
            reinterpret_cast<const unsigned long long*>(&v_sm[cb][ich * 34]);
        unsigned long long c0a = 0ull, c0b = 0ull, c1a = 0ull, c1b = 0ull;
#pragma unroll
        for (int k = 0; k < 8; ++k) {
            const unsigned long long va = V[2 * k], vb = V[2 * k + 1];
            fma2_(c0a, va, A0[2 * k]);
            fma2_(c1a, va, A1[2 * k]);
            fma2_(c0b, vb, A0[2 * k + 1]);
            fma2_(c1b, vb, A1[2 * k + 1]);
        }
        float x0, y0, x1, y1;
        upk2(add2_(c0a, c0b), x0, y0);
        upk2(add2_(c1a, c1b), x1, y1);
        float acc0 = x0 + y0;
        float acc1 = x1 + y1;
        // butterfly across the 4 i-chunks (tid^1, tid^2 flip only ich)
        acc0 += __shfl_xor_sync(0xffffffffu, acc0, 1);
        acc1 += __shfl_xor_sync(0xffffffffu, acc1, 1);
        acc0 += __shfl_xor_sync(0xffffffffu, acc0, 2);
        acc1 += __shfl_xor_sync(0xffffffffu, acc1, 2);

        const float un0 = acc0 * (p0 * sc);
        const float un1 = acc1 * (p1 * sc);

        // publish block max every 8th step (consumed at t+1)
        if ((t & 7) == 0) {
            const int im = __reduce_max_sync(0xffffffffu, __float_as_int(fmaxf(un0, un1)));
            if ((tid & 31) == 0) wm[warp] = __int_as_float(im);
        }
        if (ich == 0) {
            float2 w; w.x = un0; w.y = un1;
            *reinterpret_cast<float2*>(&v_sm[nb][wslot]) = w;
        }
        __syncthreads();
    }

    // ---- finalize: out[b] = -ln2 * (log2(sum_j v_j) + L) ----
    const int fb = (T - 1) & 1;
    float vv = 0.f;
    if (tid < 128) vv = v_sm[fb][((tid >> 5) * 34) + (tid & 31)];
#pragma unroll
    for (int o = 16; o; o >>= 1) vv += __shfl_xor_sync(0xffffffffu, vv, o);
    if (tid < 128 && (tid & 31) == 0) wsum[tid >> 5] = vv;
    __syncthreads();
    if (tid == 0) {
        const float s = (wsum[0] + wsum[1]) + (wsum[2] + wsum[3]);
        out[b] = -LN2_F * (lg2f_(s) + (float)L);
    }
}

extern "C" void kernel_launch(void* const* d_in, const int* in_sizes, int n_in,
                              void* d_out, int out_size)
{
    const float* obs  = (const float*)d_in[0];   // [B, T, S] f32
    const float* logA = (const float*)d_in[1];   // [S, S]   f32
    float* out = (float*)d_out;                  // [B]      f32

    const int B = out_size;
    const int S = 128;
    const int T = in_sizes[0] / (B * S);

    crf_fwd_kernel<<<B, 256>>>(obs, logA, out, T);
}